// round 4
// baseline (speedup 1.0000x reference)
#include <cuda_runtime.h>
#include <stdint.h>

#define N_HITS  8192
#define E_MAXSZ 8192
#define ROW_CAP 64
#define LIST_CAP 64

// Output layout (float32 elements), tuple flattened in order:
// X (8192x3), Ri (8192x8192), Ro (8192x8192), y (8192), edges (8192x2), edge_mask (8192)
#define OFF_X     ((size_t)0)
#define OFF_RI    ((size_t)24576)
#define OFF_RO    (OFF_RI + (size_t)N_HITS * (size_t)E_MAXSZ)
#define OFF_Y     (OFF_RO + (size_t)N_HITS * (size_t)E_MAXSZ)
#define OFF_EDGES (OFF_Y + (size_t)E_MAXSZ)
#define OFF_MASK  (OFF_EDGES + (size_t)2 * E_MAXSZ)

// Distributed zeroing of the 16384 Ri/Ro rows across the pipeline kernels.
// rows [0, 8192)      -> Ri row r
// rows [8192, 16384)  -> Ro row r-8192
#define ZPREP   2048   // rows [0, 2048)          zeroed in k_prep
#define ZPAIRS  2560   // rows [2048, 4608)       zeroed in k_pairs
#define ZSCAN   2048   // rows [4608, 6656)       zeroed in k_scan
#define ZEMIT   2048   // rows [6656, 8704)       zeroed in k_emit
#define EARLY_TOTAL (ZPREP + ZPAIRS + ZSCAN + ZEMIT)   // 8704; rest in k_final

// ---- scratch (device globals; zero-initialized at module load) ----
__device__ float  g_phin[N_HITS];
__device__ float  g_zn[N_HITS];
__device__ float  g_track[N_HITS];
__device__ int    g_trkInt[N_HITS];
__device__ float  g_ev[N_HITS];
__device__ int    g_st[N_HITS];

__device__ int    g_stcnt[32];              // reset at end of k_final (post last reader)
__device__ float4 g_stdata[32][N_HITS];     // {phin, zn, idx_bits, ev}

__device__ int    g_rowcnt[N_HITS];
__device__ int    g_rowoff[N_HITS];
__device__ int    g_count;
__device__ int    g_rowj[N_HITS][ROW_CAP];

// per-track edge lists for the zero+scatter pass (reset in k_prep)
__device__ int    g_inCnt[1024];            // edges e with track[dst[e]] == t  -> Ri rows
__device__ int    g_outCnt[1024];           // edges e with track[src[e]] == t  -> Ro rows
__device__ int    g_inList[1024][LIST_CAP];
__device__ int    g_outList[1024][LIST_CAP];

// ---------------------------------------------------------------------------
// bulk zero one 8192-float matrix row (works for any blockDim)
// ---------------------------------------------------------------------------
__device__ __forceinline__ void zero_row(float* __restrict__ out, int row) {
    size_t base = (row < N_HITS)
        ? OFF_RI + (size_t)row * E_MAXSZ
        : OFF_RO + (size_t)(row - N_HITS) * E_MAXSZ;
    float4* p = (float4*)(out + base);
    const float4 z4 = make_float4(0.f, 0.f, 0.f, 0.f);
    for (int k = threadIdx.x; k < E_MAXSZ / 4; k += blockDim.x)
        p[k] = z4;
}

// ---------------------------------------------------------------------------
// K1: per-hit normalize (write X), station bucket; extra blocks zero rows.
// grid = 32 + ZPREP, block = 256
// ---------------------------------------------------------------------------
__global__ void __launch_bounds__(256) k_prep(const float* __restrict__ ed,
                                              float* __restrict__ out) {
    int bid = blockIdx.x;
    if (bid >= 32) {                 // zero role
        zero_row(out, bid - 32);     // rows [0, ZPREP)
        return;
    }
    int i = bid * 256 + threadIdx.x;

    // reset per-track edge counters for this run (safe: producers/consumers
    // of these counters are in later kernels, stream-ordered after k_prep)
    if (i < 1024) { g_inCnt[i] = 0; g_outCnt[i] = 0; }

    float ev  = ed[6 * i + 0];
    float x   = ed[6 * i + 1];
    float y   = ed[6 * i + 2];
    float z   = ed[6 * i + 3];
    float stf = ed[6 * i + 4];
    float trk = ed[6 * i + 5];

    // IEEE-exact f32 path (no fma contraction, rn division/sqrt)
    float xx = __fmul_rn(x, x);
    float yy = __fmul_rn(y, y);
    float r  = __fsqrt_rn(__fadd_rn(xx, yy));
    float phi = atan2f(x, y);

    float rn   = __fadd_rn(__fdiv_rn(__fmul_rn(2.0f, __fadd_rn(r,  -269.0f)),  312.0f), -1.0f);
    float phin = __fadd_rn(__fdiv_rn(__fmul_rn(2.0f, __fadd_rn(phi,  3.15f)),    6.3f), -1.0f);
    float zn   = __fadd_rn(__fdiv_rn(__fmul_rn(2.0f, __fadd_rn(z,  2386.0f)),  4772.0f), -1.0f);

    out[OFF_X + 3 * (size_t)i + 0] = rn;
    out[OFF_X + 3 * (size_t)i + 1] = phin;
    out[OFF_X + 3 * (size_t)i + 2] = zn;

    g_phin[i]   = phin;
    g_zn[i]     = zn;
    g_track[i]  = trk;
    g_trkInt[i] = (int)trk;
    g_ev[i]     = ev;
    int st      = (int)stf;
    g_st[i]     = st;

    if (st >= 0 && st < 32) {
        int slot = atomicAdd(&g_stcnt[st], 1);
        float4 d;
        d.x = phin; d.y = zn; d.z = __int_as_float(i); d.w = ev;
        g_stdata[st][slot] = d;
    }
}

// ---------------------------------------------------------------------------
// K2: warp-per-row candidate scan against station st+1; sort matches by j.
// grid = 1024 + ZPAIRS, block = 256 (8 warps -> 8 rows per pairs-block)
// ---------------------------------------------------------------------------
__global__ void __launch_bounds__(256) k_pairs(float* __restrict__ out) {
    int bid = blockIdx.x;
    if (bid >= 1024) {
        zero_row(out, ZPREP + (bid - 1024));   // rows [ZPREP, ZPREP+ZPAIRS)
        return;
    }
    int gtid = bid * 256 + threadIdx.x;
    int row  = gtid >> 5;
    int lane = gtid & 31;

    int myMatch[16];
    int mycnt = 0;

    int s2 = g_st[row] + 1;
    if (s2 >= 0 && s2 < 32) {
        int n2 = g_stcnt[s2];
        float pi  = g_phin[row];
        float zi  = g_zn[row];
        float evi = g_ev[row];
        for (int k = lane; k < n2; k += 32) {
            float4 c = g_stdata[s2][k];
            float dphi = c.x - pi;
            float dz   = c.y - zi;
            bool ok = (c.w == evi) &
                      (dphi > -0.04f) & (dphi < 0.04f) &
                      (dz   > -0.03f) & (dz   < 0.03f);
            if (ok && mycnt < 16) myMatch[mycnt++] = __float_as_int(c.z);
        }
    }

    // warp exclusive scan of per-lane counts
    int off = mycnt;
    #pragma unroll
    for (int d = 1; d < 32; d <<= 1) {
        int v = __shfl_up_sync(0xFFFFFFFFu, off, d);
        if (lane >= d) off += v;
    }
    int total = __shfl_sync(0xFFFFFFFFu, off, 31);
    int excl  = off - mycnt;
    for (int m = 0; m < mycnt; m++) {
        int e = excl + m;
        if (e < ROW_CAP) g_rowj[row][e] = myMatch[m];
    }
    __syncwarp();

    if (lane == 0) {
        int cnt = total < ROW_CAP ? total : ROW_CAP;
        // insertion sort ascending by j (bucket order is nondeterministic;
        // this restores exact row-major nonzero order)
        for (int a = 1; a < cnt; a++) {
            int v = g_rowj[row][a];
            int b = a - 1;
            while (b >= 0 && g_rowj[row][b] > v) { g_rowj[row][b + 1] = g_rowj[row][b]; b--; }
            g_rowj[row][b + 1] = v;
        }
        g_rowcnt[row] = cnt;
    }
}

// ---------------------------------------------------------------------------
// K3: global scan (block 0, 1024 thr, 8 rows/thread); extra blocks zero rows.
// grid = 1 + ZSCAN, block = 1024
// ---------------------------------------------------------------------------
__global__ void __launch_bounds__(1024) k_scan(float* __restrict__ out) {
    if (blockIdx.x > 0) {
        zero_row(out, ZPREP + ZPAIRS + (int)(blockIdx.x - 1));
        return;
    }
    __shared__ int warpTot[32];
    int tid  = threadIdx.x;
    int lane = tid & 31;
    int wid  = tid >> 5;

    int base = tid * 8;
    int4 a = *(const int4*)&g_rowcnt[base];
    int4 b = *(const int4*)&g_rowcnt[base + 4];
    int loc[8] = {a.x, a.y, a.z, a.w, b.x, b.y, b.z, b.w};
    int acc = 0;
    #pragma unroll
    for (int m = 0; m < 8; m++) acc += loc[m];

    int inc = acc;
    #pragma unroll
    for (int d = 1; d < 32; d <<= 1) {
        int v = __shfl_up_sync(0xFFFFFFFFu, inc, d);
        if (lane >= d) inc += v;
    }
    if (lane == 31) warpTot[wid] = inc;
    __syncthreads();
    if (wid == 0) {
        int w = warpTot[lane];
        int wi = w;
        #pragma unroll
        for (int d = 1; d < 32; d <<= 1) {
            int v = __shfl_up_sync(0xFFFFFFFFu, wi, d);
            if (lane >= d) wi += v;
        }
        warpTot[lane] = wi - w;
        if (lane == 31) g_count = wi;
    }
    __syncthreads();
    int run = inc - acc + warpTot[wid];
    int off8[8];
    #pragma unroll
    for (int m = 0; m < 8; m++) { off8[m] = run; run += loc[m]; }
    *(int4*)&g_rowoff[base]     = make_int4(off8[0], off8[1], off8[2], off8[3]);
    *(int4*)&g_rowoff[base + 4] = make_int4(off8[4], off8[5], off8[6], off8[7]);
}

// ---------------------------------------------------------------------------
// K4: wide emit — one thread per row: edges, per-track lists, fill/mask/y.
// grid = 32 + ZEMIT, block = 256
// ---------------------------------------------------------------------------
__global__ void __launch_bounds__(256) k_emit(float* __restrict__ out) {
    int bid = blockIdx.x;
    if (bid >= 32) {
        zero_row(out, ZPREP + ZPAIRS + ZSCAN + (bid - 32));
        return;
    }
    int i = bid * 256 + threadIdx.x;

    int count = g_count;
    int cnt   = g_rowcnt[i];
    int off   = g_rowoff[i];
    float ti  = g_track[i];
    int tsI   = g_trkInt[i];

    for (int q = 0; q < cnt; q++) {
        int e = off + q;
        if (e < E_MAXSZ) {
            int j = g_rowj[i][q];
            out[OFF_EDGES + 2 * (size_t)e + 0] = ti;
            out[OFF_EDGES + 2 * (size_t)e + 1] = g_track[j];
            int tdI = g_trkInt[j];
            int so = atomicAdd(&g_outCnt[tsI], 1);
            if (so < LIST_CAP) g_outList[tsI][so] = e;
            int si = atomicAdd(&g_inCnt[tdI], 1);
            if (si < LIST_CAP) g_inList[tdI][si] = e;
        }
    }

    // slot i bookkeeping: y, mask, fill (nonzero fill_value=0 -> track[0])
    out[OFF_Y + (size_t)i] = 0.0f;
    out[OFF_MASK + (size_t)i] = (i < count) ? 1.0f : 0.0f;
    if (i >= count) {
        float t0 = g_track[0];
        out[OFF_EDGES + 2 * (size_t)i + 0] = t0;
        out[OFF_EDGES + 2 * (size_t)i + 1] = t0;
    }
}

// ---------------------------------------------------------------------------
// K5: finish — late rows: zero + scatter ones (fused); early rows: scatter
// only (their zeros landed in earlier kernels). Also resets g_stcnt for the
// next replay (safe: no k_final block reads it).
// grid = 16384, block = 256
// ---------------------------------------------------------------------------
__global__ void __launch_bounds__(256) k_final(float* __restrict__ out) {
    int row = blockIdx.x;
    int tid = threadIdx.x;

    if (row == 0 && tid < 32) g_stcnt[tid] = 0;

    bool late = (row >= EARLY_TOTAL);
    if (late) {
        zero_row(out, row);
        __syncthreads();
    }

    int mat = row >> 13;              // 0 = Ri, 1 = Ro
    int r   = row & (N_HITS - 1);
    size_t base = (mat == 0 ? OFF_RI : OFF_RO) + (size_t)r * E_MAXSZ;

    int t = g_trkInt[r];
    int c;
    const int* lst;
    if (mat == 0) { c = g_inCnt[t];  lst = g_inList[t];  }
    else          { c = g_outCnt[t]; lst = g_outList[t]; }
    if (c > LIST_CAP) c = LIST_CAP;
    for (int m = tid; m < c; m += 256)
        out[base + (size_t)lst[m]] = 1.0f;
}

// ---------------------------------------------------------------------------
extern "C" void kernel_launch(void* const* d_in, const int* in_sizes, int n_in,
                              void* d_out, int out_size) {
    const float* ed = (const float*)d_in[0];
    float* out = (float*)d_out;

    k_prep <<<32 + ZPREP,   256>>>(ed, out);
    k_pairs<<<1024 + ZPAIRS, 256>>>(out);
    k_scan <<<1 + ZSCAN,    1024>>>(out);
    k_emit <<<32 + ZEMIT,   256>>>(out);
    k_final<<<16384,        256>>>(out);
}

// round 5
// speedup vs baseline: 1.0457x; 1.0457x over previous
#include <cuda_runtime.h>
#include <stdint.h>

#define N_HITS  8192
#define E_MAXSZ 8192
#define ROW_CAP 64
#define LIST_CAP 64

// Output layout (float32 elements), tuple flattened in order:
// X (8192x3), Ri (8192x8192), Ro (8192x8192), y (8192), edges (8192x2), edge_mask (8192)
#define OFF_X     ((size_t)0)
#define OFF_RI    ((size_t)24576)
#define OFF_RO    (OFF_RI + (size_t)N_HITS * (size_t)E_MAXSZ)
#define OFF_Y     (OFF_RO + (size_t)N_HITS * (size_t)E_MAXSZ)
#define OFF_EDGES (OFF_Y + (size_t)E_MAXSZ)
#define OFF_MASK  (OFF_EDGES + (size_t)2 * E_MAXSZ)

// ---- scratch (device globals; zero-initialized at module load) ----
__device__ float  g_phin[N_HITS];
__device__ float  g_zn[N_HITS];
__device__ float  g_track[N_HITS];
__device__ int    g_trkInt[N_HITS];
__device__ float  g_ev[N_HITS];
__device__ int    g_st[N_HITS];

__device__ int    g_stcnt[32];              // reset in k_final (after last reader)
__device__ float4 g_stdata[32][N_HITS];     // {phin, zn, idx_bits, ev}

__device__ int    g_rowcnt[N_HITS];
__device__ int    g_rowj[N_HITS][ROW_CAP];

// per-track edge lists for the zero+scatter pass (reset in k_prep)
__device__ int    g_inCnt[1024];            // edges e with track[dst[e]] == t  -> Ri rows
__device__ int    g_outCnt[1024];           // edges e with track[src[e]] == t  -> Ro rows
__device__ int    g_inList[1024][LIST_CAP];
__device__ int    g_outList[1024][LIST_CAP];

// ---------------------------------------------------------------------------
// K1: per-hit normalize (write X), station bucket; also resets edge counters.
// grid = 32, block = 256
// ---------------------------------------------------------------------------
__global__ void __launch_bounds__(256) k_prep(const float* __restrict__ ed,
                                              float* __restrict__ out) {
    int i = blockIdx.x * 256 + threadIdx.x;

    // reset per-track edge counters for this run (their producers/consumers
    // live in later, stream-ordered kernels)
    if (i < 1024) { g_inCnt[i] = 0; g_outCnt[i] = 0; }

    float ev  = ed[6 * i + 0];
    float x   = ed[6 * i + 1];
    float y   = ed[6 * i + 2];
    float z   = ed[6 * i + 3];
    float stf = ed[6 * i + 4];
    float trk = ed[6 * i + 5];

    // IEEE-exact f32 path (no fma contraction, rn division/sqrt)
    float xx = __fmul_rn(x, x);
    float yy = __fmul_rn(y, y);
    float r  = __fsqrt_rn(__fadd_rn(xx, yy));
    float phi = atan2f(x, y);

    float rn   = __fadd_rn(__fdiv_rn(__fmul_rn(2.0f, __fadd_rn(r,  -269.0f)),  312.0f), -1.0f);
    float phin = __fadd_rn(__fdiv_rn(__fmul_rn(2.0f, __fadd_rn(phi,  3.15f)),    6.3f), -1.0f);
    float zn   = __fadd_rn(__fdiv_rn(__fmul_rn(2.0f, __fadd_rn(z,  2386.0f)),  4772.0f), -1.0f);

    out[OFF_X + 3 * (size_t)i + 0] = rn;
    out[OFF_X + 3 * (size_t)i + 1] = phin;
    out[OFF_X + 3 * (size_t)i + 2] = zn;

    g_phin[i]   = phin;
    g_zn[i]     = zn;
    g_track[i]  = trk;
    g_trkInt[i] = (int)trk;
    g_ev[i]     = ev;
    int st      = (int)stf;
    g_st[i]     = st;

    if (st >= 0 && st < 32) {
        int slot = atomicAdd(&g_stcnt[st], 1);
        float4 d;
        d.x = phin; d.y = zn; d.z = __int_as_float(i); d.w = ev;
        g_stdata[st][slot] = d;
    }
}

// ---------------------------------------------------------------------------
// K2: warp-per-row candidate scan against station st+1; sort matches by j.
// grid = 1024, block = 256 (8 warps -> 8 rows per block)
// ---------------------------------------------------------------------------
__global__ void __launch_bounds__(256) k_pairs(void) {
    int gtid = blockIdx.x * 256 + threadIdx.x;
    int row  = gtid >> 5;
    int lane = gtid & 31;

    int myMatch[16];
    int mycnt = 0;

    int s2 = g_st[row] + 1;
    if (s2 >= 0 && s2 < 32) {
        int n2 = g_stcnt[s2];
        float pi  = g_phin[row];
        float zi  = g_zn[row];
        float evi = g_ev[row];
        for (int k = lane; k < n2; k += 32) {
            float4 c = g_stdata[s2][k];
            float dphi = c.x - pi;
            float dz   = c.y - zi;
            bool ok = (c.w == evi) &
                      (dphi > -0.04f) & (dphi < 0.04f) &
                      (dz   > -0.03f) & (dz   < 0.03f);
            if (ok && mycnt < 16) myMatch[mycnt++] = __float_as_int(c.z);
        }
    }

    // warp exclusive scan of per-lane counts
    int off = mycnt;
    #pragma unroll
    for (int d = 1; d < 32; d <<= 1) {
        int v = __shfl_up_sync(0xFFFFFFFFu, off, d);
        if (lane >= d) off += v;
    }
    int total = __shfl_sync(0xFFFFFFFFu, off, 31);
    int excl  = off - mycnt;
    for (int m = 0; m < mycnt; m++) {
        int e = excl + m;
        if (e < ROW_CAP) g_rowj[row][e] = myMatch[m];
    }
    __syncwarp();

    if (lane == 0) {
        int cnt = total < ROW_CAP ? total : ROW_CAP;
        // insertion sort ascending by j (bucket order is nondeterministic;
        // this restores exact row-major nonzero order)
        for (int a = 1; a < cnt; a++) {
            int v = g_rowj[row][a];
            int b = a - 1;
            while (b >= 0 && g_rowj[row][b] > v) { g_rowj[row][b + 1] = g_rowj[row][b]; b--; }
            g_rowj[row][b + 1] = v;
        }
        g_rowcnt[row] = cnt;
    }
}

// ---------------------------------------------------------------------------
// K3: emit with fused (redundant per-block) global scan.
// grid = 32, block = 256. Each block loads all 8192 row counts into smem,
// scans them, then emits rows [bid*256, bid*256+256).
// ---------------------------------------------------------------------------
__global__ void __launch_bounds__(256) k_emit(float* __restrict__ out) {
    __shared__ int s_cnt[N_HITS];        // 32 KB
    __shared__ int s_chunkOff[256];
    __shared__ int s_warpTot[8];
    __shared__ int s_count;

    int tid  = threadIdx.x;
    int lane = tid & 31;
    int wid  = tid >> 5;
    int bid  = blockIdx.x;

    // load all counts (coalesced int4)
    #pragma unroll
    for (int k = 0; k < 8; k++) {
        int idx = (k * 256 + tid) * 4;
        *(int4*)&s_cnt[idx] = *(const int4*)&g_rowcnt[idx];
    }
    __syncthreads();

    // thread t sums chunk [t*32, t*32+32)
    int acc = 0;
    int cbase = tid * 32;
    #pragma unroll
    for (int m = 0; m < 32; m++) acc += s_cnt[cbase + m];

    // block scan over 256 chunk sums
    int inc = acc;
    #pragma unroll
    for (int d = 1; d < 32; d <<= 1) {
        int v = __shfl_up_sync(0xFFFFFFFFu, inc, d);
        if (lane >= d) inc += v;
    }
    if (lane == 31) s_warpTot[wid] = inc;
    __syncthreads();
    if (wid == 0 && lane < 8) {
        int w = s_warpTot[lane];
        int wi = w;
        #pragma unroll
        for (int d = 1; d < 8; d <<= 1) {
            int v = __shfl_up_sync(0xFFu, wi, d);
            if (lane >= d) wi += v;
        }
        s_warpTot[lane] = wi - w;
        if (lane == 7) s_count = wi;
    }
    __syncthreads();
    s_chunkOff[tid] = inc - acc + s_warpTot[wid];
    __syncthreads();

    int count = s_count;

    // this thread emits row i = bid*256 + tid
    int i = bid * 256 + tid;
    int chunk = i >> 5;                      // i/32
    int off = s_chunkOff[chunk];
    for (int m = chunk * 32; m < i; m++) off += s_cnt[m];

    int cnt  = s_cnt[i];
    float ti = g_track[i];
    int tsI  = g_trkInt[i];

    for (int q = 0; q < cnt; q++) {
        int e = off + q;
        if (e < E_MAXSZ) {
            int j = g_rowj[i][q];
            out[OFF_EDGES + 2 * (size_t)e + 0] = ti;
            out[OFF_EDGES + 2 * (size_t)e + 1] = g_track[j];
            int tdI = g_trkInt[j];
            int so = atomicAdd(&g_outCnt[tsI], 1);
            if (so < LIST_CAP) g_outList[tsI][so] = e;
            int si = atomicAdd(&g_inCnt[tdI], 1);
            if (si < LIST_CAP) g_inList[tdI][si] = e;
        }
    }

    // slot i bookkeeping: y, mask, fill (nonzero fill_value=0 -> track[0])
    out[OFF_Y + (size_t)i] = 0.0f;
    out[OFF_MASK + (size_t)i] = (i < count) ? 1.0f : 0.0f;
    if (i >= count) {
        float t0 = g_track[0];
        out[OFF_EDGES + 2 * (size_t)i + 0] = t0;
        out[OFF_EDGES + 2 * (size_t)i + 1] = t0;
    }
}

// ---------------------------------------------------------------------------
// K4: fused zero + ones for Ri and Ro. One block per matrix row.
// blockIdx [0,8192)     -> Ri row
// blockIdx [8192,16384) -> Ro row
// Also resets g_stcnt for the next replay (after its last reader this run).
// ---------------------------------------------------------------------------
__global__ void __launch_bounds__(256) k_final(float* __restrict__ out) {
    int bid = blockIdx.x;
    int mat = bid >> 13;          // 0 = Ri, 1 = Ro
    int row = bid & (N_HITS - 1);
    int tid = threadIdx.x;

    if (bid == 0 && tid < 32) g_stcnt[tid] = 0;

    size_t base = (mat == 0 ? OFF_RI : OFF_RO) + (size_t)row * E_MAXSZ;
    float4* p = (float4*)(out + base);
    const float4 z4 = make_float4(0.f, 0.f, 0.f, 0.f);
    #pragma unroll
    for (int k = 0; k < 8; k++)
        p[k * 256 + tid] = z4;

    __syncthreads();

    int t = g_trkInt[row];
    int c;
    const int* lst;
    if (mat == 0) { c = g_inCnt[t];  lst = g_inList[t];  }
    else          { c = g_outCnt[t]; lst = g_outList[t]; }
    if (c > LIST_CAP) c = LIST_CAP;
    for (int m = tid; m < c; m += 256)
        out[base + (size_t)lst[m]] = 1.0f;
}

// ---------------------------------------------------------------------------
extern "C" void kernel_launch(void* const* d_in, const int* in_sizes, int n_in,
                              void* d_out, int out_size) {
    const float* ed = (const float*)d_in[0];
    float* out = (float*)d_out;

    k_prep <<<32,    256>>>(ed, out);
    k_pairs<<<1024,  256>>>();
    k_emit <<<32,    256>>>(out);
    k_final<<<16384, 256>>>(out);
}

// round 6
// speedup vs baseline: 1.0843x; 1.0370x over previous
#include <cuda_runtime.h>
#include <stdint.h>

#define N_HITS  8192
#define E_MAXSZ 8192
#define ROW_CAP 64
#define LIST_CAP 64
#define NBLK 512
#define ROWS_PER_BLK 16     // 512 * 16 = 8192

// Output layout (float32 elements), tuple flattened in order:
// X (8192x3), Ri (8192x8192), Ro (8192x8192), y (8192), edges (8192x2), edge_mask (8192)
#define OFF_X     ((size_t)0)
#define OFF_RI    ((size_t)24576)
#define OFF_RO    (OFF_RI + (size_t)N_HITS * (size_t)E_MAXSZ)
#define OFF_Y     (OFF_RO + (size_t)N_HITS * (size_t)E_MAXSZ)
#define OFF_EDGES (OFF_Y + (size_t)E_MAXSZ)
#define OFF_MASK  (OFF_EDGES + (size_t)2 * E_MAXSZ)

// ---- scratch (device globals; zero-initialized at module load) ----
__device__ float  g_phin[N_HITS];
__device__ float  g_zn[N_HITS];
__device__ float  g_track[N_HITS];
__device__ int    g_trkInt[N_HITS];
__device__ float  g_ev[N_HITS];
__device__ int    g_st[N_HITS];

__device__ int    g_stcnt[32];              // reset in k_final (after last reader)
__device__ float4 g_stdata[32][N_HITS];     // {phin, zn, idx_bits, ev}

__device__ int    g_blockSum[NBLK];

// per-track edge lists for the zero+scatter pass
__device__ int    g_inCnt[1024];            // edges e with track[dst[e]] == t  -> Ri rows
__device__ int    g_outCnt[1024];           // edges e with track[src[e]] == t  -> Ro rows
__device__ int    g_inList[1024][LIST_CAP];
__device__ int    g_outList[1024][LIST_CAP];

// spin-barrier counters (reset in k_final for the next replay)
__device__ int    g_barA;
__device__ int    g_barB;

// ---------------------------------------------------------------------------
// grid-wide barrier for exactly NBLK co-resident blocks
// ---------------------------------------------------------------------------
__device__ __forceinline__ void grid_bar(int* ctr) {
    __syncthreads();
    if (threadIdx.x == 0) {
        __threadfence();                       // release: publish prior writes
        atomicAdd(ctr, 1);
        while (*(volatile int*)ctr < NBLK) { }
        __threadfence();                       // acquire
    }
    __syncthreads();
}

// ---------------------------------------------------------------------------
// K1: fused pipeline — phase0 prep, phase1 pairs, phase2 scan+emit.
// grid = NBLK(512), block = 256. __launch_bounds__(256,4) guarantees all 512
// blocks co-resident (4/SM * 148 = 592 slots), making the spin barriers safe.
// ---------------------------------------------------------------------------
__global__ void __launch_bounds__(256, 4) k_pipeline(const float* __restrict__ ed,
                                                     float* __restrict__ out) {
    __shared__ int s_rowj[ROWS_PER_BLK][ROW_CAP];   // 4 KB
    __shared__ int s_rowcnt[ROWS_PER_BLK];
    __shared__ int s_bs[NBLK];                      // 2 KB
    __shared__ int s_pfx[256];                      // 1 KB (pair prefixes)
    __shared__ int s_wt[8];
    __shared__ int s_count;

    int tid  = threadIdx.x;
    int lane = tid & 31;
    int wid  = tid >> 5;
    int bid  = blockIdx.x;

    // ===== Phase 0: prep (this block's 16 hits) + counter reset =====
    if (tid < ROWS_PER_BLK) {
        int i = bid * ROWS_PER_BLK + tid;

        float ev  = ed[6 * i + 0];
        float x   = ed[6 * i + 1];
        float y   = ed[6 * i + 2];
        float z   = ed[6 * i + 3];
        float stf = ed[6 * i + 4];
        float trk = ed[6 * i + 5];

        // IEEE-exact f32 path (no fma contraction, rn division/sqrt)
        float xx = __fmul_rn(x, x);
        float yy = __fmul_rn(y, y);
        float r  = __fsqrt_rn(__fadd_rn(xx, yy));
        float phi = atan2f(x, y);

        float rn   = __fadd_rn(__fdiv_rn(__fmul_rn(2.0f, __fadd_rn(r,  -269.0f)),  312.0f), -1.0f);
        float phin = __fadd_rn(__fdiv_rn(__fmul_rn(2.0f, __fadd_rn(phi,  3.15f)),    6.3f), -1.0f);
        float zn   = __fadd_rn(__fdiv_rn(__fmul_rn(2.0f, __fadd_rn(z,  2386.0f)),  4772.0f), -1.0f);

        out[OFF_X + 3 * (size_t)i + 0] = rn;
        out[OFF_X + 3 * (size_t)i + 1] = phin;
        out[OFF_X + 3 * (size_t)i + 2] = zn;

        g_phin[i]   = phin;
        g_zn[i]     = zn;
        g_track[i]  = trk;
        g_trkInt[i] = (int)trk;
        g_ev[i]     = ev;
        int st      = (int)stf;
        g_st[i]     = st;

        if (st >= 0 && st < 32) {
            int slot = atomicAdd(&g_stcnt[st], 1);
            float4 d;
            d.x = phin; d.y = zn; d.z = __int_as_float(i); d.w = ev;
            g_stdata[st][slot] = d;
        }
    }
    if (tid < 2) { g_inCnt[bid * 2 + tid] = 0; g_outCnt[bid * 2 + tid] = 0; }

    grid_bar(&g_barA);

    // ===== Phase 1: pairs — warp w handles local rows w and w+8 =====
    #pragma unroll
    for (int half = 0; half < 2; half++) {
        int local = wid + half * 8;
        int row   = bid * ROWS_PER_BLK + local;

        int myMatch[16];
        int mycnt = 0;

        int s2 = g_st[row] + 1;
        if (s2 >= 0 && s2 < 32) {
            int n2 = g_stcnt[s2];
            float pi  = g_phin[row];
            float zi  = g_zn[row];
            float evi = g_ev[row];
            for (int k = lane; k < n2; k += 32) {
                float4 c = g_stdata[s2][k];
                float dphi = c.x - pi;
                float dz   = c.y - zi;
                bool ok = (c.w == evi) &
                          (dphi > -0.04f) & (dphi < 0.04f) &
                          (dz   > -0.03f) & (dz   < 0.03f);
                if (ok && mycnt < 16) myMatch[mycnt++] = __float_as_int(c.z);
            }
        }

        // warp exclusive scan of per-lane counts
        int off = mycnt;
        #pragma unroll
        for (int d = 1; d < 32; d <<= 1) {
            int v = __shfl_up_sync(0xFFFFFFFFu, off, d);
            if (lane >= d) off += v;
        }
        int total = __shfl_sync(0xFFFFFFFFu, off, 31);
        int excl  = off - mycnt;
        for (int m = 0; m < mycnt; m++) {
            int e = excl + m;
            if (e < ROW_CAP) s_rowj[local][e] = myMatch[m];
        }
        __syncwarp();

        if (lane == 0) {
            int cnt = total < ROW_CAP ? total : ROW_CAP;
            // insertion sort ascending by j (bucket order nondeterministic;
            // restores exact row-major nonzero order)
            for (int a = 1; a < cnt; a++) {
                int v = s_rowj[local][a];
                int b = a - 1;
                while (b >= 0 && s_rowj[local][b] > v) { s_rowj[local][b + 1] = s_rowj[local][b]; b--; }
                s_rowj[local][b + 1] = v;
            }
            s_rowcnt[local] = cnt;
        }
        __syncwarp();
    }

    __syncthreads();
    if (tid == 0) {
        int sum = 0;
        #pragma unroll
        for (int m = 0; m < ROWS_PER_BLK; m++) sum += s_rowcnt[m];
        g_blockSum[bid] = sum;
    }

    grid_bar(&g_barB);

    // ===== Phase 2: decoupled scan of block sums, then emit =====
    s_bs[tid]       = g_blockSum[tid];
    s_bs[tid + 256] = g_blockSum[tid + 256];
    __syncthreads();

    int pairSum = s_bs[2 * tid] + s_bs[2 * tid + 1];
    int inc = pairSum;
    #pragma unroll
    for (int d = 1; d < 32; d <<= 1) {
        int v = __shfl_up_sync(0xFFFFFFFFu, inc, d);
        if (lane >= d) inc += v;
    }
    if (lane == 31) s_wt[wid] = inc;
    __syncthreads();
    if (wid == 0 && lane < 8) {
        int w = s_wt[lane];
        int wi = w;
        #pragma unroll
        for (int d = 1; d < 8; d <<= 1) {
            int v = __shfl_up_sync(0xFFu, wi, d);
            if (lane >= d) wi += v;
        }
        s_wt[lane] = wi - w;      // exclusive warp offsets
        if (lane == 7) s_count = wi;
    }
    __syncthreads();
    int pairExcl = inc - pairSum + s_wt[wid];
    s_pfx[tid] = pairExcl;
    __syncthreads();

    int count   = s_count;
    int blkBase = s_pfx[bid >> 1] + ((bid & 1) ? s_bs[bid - 1] : 0);

    // emit: warp w handles local rows w and w+8
    #pragma unroll
    for (int half = 0; half < 2; half++) {
        int local = wid + half * 8;
        int row   = bid * ROWS_PER_BLK + local;
        int cnt   = s_rowcnt[local];

        int off = blkBase;
        for (int m = 0; m < local; m++) off += s_rowcnt[m];

        float ti = g_track[row];
        int  tsI = g_trkInt[row];

        for (int q = lane; q < cnt; q += 32) {
            int e = off + q;
            if (e < E_MAXSZ) {
                int j = s_rowj[local][q];
                out[OFF_EDGES + 2 * (size_t)e + 0] = ti;
                out[OFF_EDGES + 2 * (size_t)e + 1] = g_track[j];
                int tdI = g_trkInt[j];
                int so = atomicAdd(&g_outCnt[tsI], 1);
                if (so < LIST_CAP) g_outList[tsI][so] = e;
                int si = atomicAdd(&g_inCnt[tdI], 1);
                if (si < LIST_CAP) g_inList[tdI][si] = e;
            }
        }
    }

    // slot bookkeeping: y, mask, fill (nonzero fill_value=0 -> track[0])
    if (tid < ROWS_PER_BLK) {
        int s = bid * ROWS_PER_BLK + tid;
        out[OFF_Y + (size_t)s] = 0.0f;
        out[OFF_MASK + (size_t)s] = (s < count) ? 1.0f : 0.0f;
        if (s >= count) {
            float t0 = g_track[0];
            out[OFF_EDGES + 2 * (size_t)s + 0] = t0;
            out[OFF_EDGES + 2 * (size_t)s + 1] = t0;
        }
    }
}

// ---------------------------------------------------------------------------
// K2: fused zero + ones for Ri and Ro. One block per matrix row.
// blockIdx [0,8192)     -> Ri row
// blockIdx [8192,16384) -> Ro row
// Also resets g_stcnt + barrier counters for the next replay.
// ---------------------------------------------------------------------------
__global__ void __launch_bounds__(256) k_final(float* __restrict__ out) {
    int bid = blockIdx.x;
    int mat = bid >> 13;          // 0 = Ri, 1 = Ro
    int row = bid & (N_HITS - 1);
    int tid = threadIdx.x;

    if (bid == 0) {
        if (tid < 32) g_stcnt[tid] = 0;
        if (tid == 32) g_barA = 0;
        if (tid == 33) g_barB = 0;
    }

    size_t base = (mat == 0 ? OFF_RI : OFF_RO) + (size_t)row * E_MAXSZ;
    float4* p = (float4*)(out + base);
    const float4 z4 = make_float4(0.f, 0.f, 0.f, 0.f);
    #pragma unroll
    for (int k = 0; k < 8; k++)
        p[k * 256 + tid] = z4;

    __syncthreads();

    int t = g_trkInt[row];
    int c;
    const int* lst;
    if (mat == 0) { c = g_inCnt[t];  lst = g_inList[t];  }
    else          { c = g_outCnt[t]; lst = g_outList[t]; }
    if (c > LIST_CAP) c = LIST_CAP;
    for (int m = tid; m < c; m += 256)
        out[base + (size_t)lst[m]] = 1.0f;
}

// ---------------------------------------------------------------------------
extern "C" void kernel_launch(void* const* d_in, const int* in_sizes, int n_in,
                              void* d_out, int out_size) {
    const float* ed = (const float*)d_in[0];
    float* out = (float*)d_out;

    k_pipeline<<<NBLK,  256>>>(ed, out);
    k_final   <<<16384, 256>>>(out);
}

// round 8
// speedup vs baseline: 1.1855x; 1.0933x over previous
#include <cuda_runtime.h>
#include <stdint.h>

#define N_HITS  8192
#define E_MAXSZ 8192
#define ROW_CAP 64
#define LIST_CAP 64
#define NBLK 512
#define ROWS_PER_BLK 16     // 512 * 16 = 8192

// Output layout (float32 elements), tuple flattened in order:
// X (8192x3), Ri (8192x8192), Ro (8192x8192), y (8192), edges (8192x2), edge_mask (8192)
#define OFF_X     ((size_t)0)
#define OFF_RI    ((size_t)24576)
#define OFF_RO    (OFF_RI + (size_t)N_HITS * (size_t)E_MAXSZ)
#define OFF_Y     (OFF_RO + (size_t)N_HITS * (size_t)E_MAXSZ)
#define OFF_EDGES (OFF_Y + (size_t)E_MAXSZ)
#define OFF_MASK  (OFF_EDGES + (size_t)2 * E_MAXSZ)

// ---- scratch (device globals; zero-initialized at module load) ----
__device__ float  g_phin[N_HITS];
__device__ float  g_zn[N_HITS];
__device__ float  g_track[N_HITS];
__device__ int    g_trkInt[N_HITS];
__device__ float  g_ev[N_HITS];
__device__ int    g_st[N_HITS];

__device__ int    g_stcnt[32];              // reset in k_scatter (after last reader)
__device__ float4 g_stdata[32][N_HITS];     // {phin, zn, idx_bits, ev}

__device__ int    g_blockSum[NBLK];

// per-track edge lists (counters reset in pipeline phase 0 each run)
__device__ int    g_inCnt[1024];            // edges e with track[dst[e]] == t  -> Ri rows
__device__ int    g_outCnt[1024];           // edges e with track[src[e]] == t  -> Ro rows
__device__ int    g_inList[1024][LIST_CAP];
__device__ int    g_outList[1024][LIST_CAP];

// spin-barrier counters (reset in k_scatter for the next replay)
__device__ int    g_barA;
__device__ int    g_barB;

// ---------------------------------------------------------------------------
// grid-wide barrier for exactly NBLK co-resident pipeline blocks.
// Zero-role blocks never touch it (they retire), so it cannot deadlock as
// long as the NBLK lowest bids are wave-1 resident (guaranteed by
// __launch_bounds__(256,4): 4 * 148 = 592 slots >= NBLK, in-order dispatch).
// ---------------------------------------------------------------------------
__device__ __forceinline__ void grid_bar(int* ctr) {
    __syncthreads();
    if (threadIdx.x == 0) {
        __threadfence();                       // release: publish prior writes
        atomicAdd(ctr, 1);
        while (*(volatile int*)ctr < NBLK) { __nanosleep(64); }
        __threadfence();                       // acquire
    }
    __syncthreads();
}

// ---------------------------------------------------------------------------
// K1: mega kernel.
//   bids [0, NBLK)            : fused pipeline (prep -> pairs -> scan+emit)
//   bids [NBLK, NBLK+16384)   : zero one Ri/Ro row and retire (no dependence
//                               on the pipeline; overlaps it for free)
// ---------------------------------------------------------------------------
__global__ void __launch_bounds__(256, 4) k_mega(const float* __restrict__ ed,
                                                 float* __restrict__ out) {
    __shared__ int s_rowj[ROWS_PER_BLK][ROW_CAP];   // 4 KB
    __shared__ int s_rowcnt[ROWS_PER_BLK];
    __shared__ int s_bs[NBLK];                      // 2 KB
    __shared__ int s_pfx[256];                      // 1 KB
    __shared__ int s_wt[8];
    __shared__ int s_count;

    int tid  = threadIdx.x;
    int bid  = blockIdx.x;

    // ===== zero role: bulk-zero one 8192-float row, then retire =====
    if (bid >= NBLK) {
        int row = bid - NBLK;
        size_t base = (row < N_HITS)
            ? OFF_RI + (size_t)row * E_MAXSZ
            : OFF_RO + (size_t)(row - N_HITS) * E_MAXSZ;
        float4* p = (float4*)(out + base);
        const float4 z4 = make_float4(0.f, 0.f, 0.f, 0.f);
        #pragma unroll
        for (int k = 0; k < 8; k++)
            p[k * 256 + tid] = z4;
        return;
    }

    int lane = tid & 31;
    int wid  = tid >> 5;

    // ===== Phase 0: prep (this block's 16 hits) + counter reset =====
    if (tid < ROWS_PER_BLK) {
        int i = bid * ROWS_PER_BLK + tid;

        float ev  = ed[6 * i + 0];
        float x   = ed[6 * i + 1];
        float y   = ed[6 * i + 2];
        float z   = ed[6 * i + 3];
        float stf = ed[6 * i + 4];
        float trk = ed[6 * i + 5];

        // IEEE-exact f32 path (no fma contraction, rn division/sqrt)
        float xx = __fmul_rn(x, x);
        float yy = __fmul_rn(y, y);
        float r  = __fsqrt_rn(__fadd_rn(xx, yy));
        float phi = atan2f(x, y);

        float rn   = __fadd_rn(__fdiv_rn(__fmul_rn(2.0f, __fadd_rn(r,  -269.0f)),  312.0f), -1.0f);
        float phin = __fadd_rn(__fdiv_rn(__fmul_rn(2.0f, __fadd_rn(phi,  3.15f)),    6.3f), -1.0f);
        float zn   = __fadd_rn(__fdiv_rn(__fmul_rn(2.0f, __fadd_rn(z,  2386.0f)),  4772.0f), -1.0f);

        out[OFF_X + 3 * (size_t)i + 0] = rn;
        out[OFF_X + 3 * (size_t)i + 1] = phin;
        out[OFF_X + 3 * (size_t)i + 2] = zn;

        g_phin[i]   = phin;
        g_zn[i]     = zn;
        g_track[i]  = trk;
        g_trkInt[i] = (int)trk;
        g_ev[i]     = ev;
        int st      = (int)stf;
        g_st[i]     = st;

        if (st >= 0 && st < 32) {
            int slot = atomicAdd(&g_stcnt[st], 1);
            float4 d;
            d.x = phin; d.y = zn; d.z = __int_as_float(i); d.w = ev;
            g_stdata[st][slot] = d;
        }
    }
    if (tid < 2) { g_inCnt[bid * 2 + tid] = 0; g_outCnt[bid * 2 + tid] = 0; }

    grid_bar(&g_barA);

    // ===== Phase 1: pairs — warp w handles local rows w and w+8 =====
    #pragma unroll
    for (int half = 0; half < 2; half++) {
        int local = wid + half * 8;
        int row   = bid * ROWS_PER_BLK + local;

        int myMatch[16];
        int mycnt = 0;

        int s2 = g_st[row] + 1;
        if (s2 >= 0 && s2 < 32) {
            int n2 = g_stcnt[s2];
            float pi  = g_phin[row];
            float zi  = g_zn[row];
            float evi = g_ev[row];
            for (int k = lane; k < n2; k += 32) {
                float4 c = g_stdata[s2][k];
                float dphi = c.x - pi;
                float dz   = c.y - zi;
                bool ok = (c.w == evi) &
                          (dphi > -0.04f) & (dphi < 0.04f) &
                          (dz   > -0.03f) & (dz   < 0.03f);
                if (ok && mycnt < 16) myMatch[mycnt++] = __float_as_int(c.z);
            }
        }

        // warp exclusive scan of per-lane counts
        int off = mycnt;
        #pragma unroll
        for (int d = 1; d < 32; d <<= 1) {
            int v = __shfl_up_sync(0xFFFFFFFFu, off, d);
            if (lane >= d) off += v;
        }
        int total = __shfl_sync(0xFFFFFFFFu, off, 31);
        int excl  = off - mycnt;
        for (int m = 0; m < mycnt; m++) {
            int e = excl + m;
            if (e < ROW_CAP) s_rowj[local][e] = myMatch[m];
        }
        __syncwarp();

        if (lane == 0) {
            int cnt = total < ROW_CAP ? total : ROW_CAP;
            // insertion sort ascending by j (bucket order nondeterministic;
            // restores exact row-major nonzero order)
            for (int a = 1; a < cnt; a++) {
                int v = s_rowj[local][a];
                int b = a - 1;
                while (b >= 0 && s_rowj[local][b] > v) { s_rowj[local][b + 1] = s_rowj[local][b]; b--; }
                s_rowj[local][b + 1] = v;
            }
            s_rowcnt[local] = cnt;
        }
        __syncwarp();
    }

    __syncthreads();
    if (tid == 0) {
        int sum = 0;
        #pragma unroll
        for (int m = 0; m < ROWS_PER_BLK; m++) sum += s_rowcnt[m];
        g_blockSum[bid] = sum;
    }

    grid_bar(&g_barB);

    // ===== Phase 2: decoupled scan of block sums, then emit =====
    s_bs[tid]       = g_blockSum[tid];
    s_bs[tid + 256] = g_blockSum[tid + 256];
    __syncthreads();

    int pairSum = s_bs[2 * tid] + s_bs[2 * tid + 1];
    int inc = pairSum;
    #pragma unroll
    for (int d = 1; d < 32; d <<= 1) {
        int v = __shfl_up_sync(0xFFFFFFFFu, inc, d);
        if (lane >= d) inc += v;
    }
    if (lane == 31) s_wt[wid] = inc;
    __syncthreads();
    if (wid == 0 && lane < 8) {
        int w = s_wt[lane];
        int wi = w;
        #pragma unroll
        for (int d = 1; d < 8; d <<= 1) {
            int v = __shfl_up_sync(0xFFu, wi, d);
            if (lane >= d) wi += v;
        }
        s_wt[lane] = wi - w;      // exclusive warp offsets
        if (lane == 7) s_count = wi;
    }
    __syncthreads();
    int pairExcl = inc - pairSum + s_wt[wid];
    s_pfx[tid] = pairExcl;
    __syncthreads();

    int count   = s_count;
    int blkBase = s_pfx[bid >> 1] + ((bid & 1) ? s_bs[bid - 1] : 0);

    // emit: warp w handles local rows w and w+8
    #pragma unroll
    for (int half = 0; half < 2; half++) {
        int local = wid + half * 8;
        int row   = bid * ROWS_PER_BLK + local;
        int cnt   = s_rowcnt[local];

        int off = blkBase;
        for (int m = 0; m < local; m++) off += s_rowcnt[m];

        float ti = g_track[row];
        int  tsI = g_trkInt[row];

        for (int q = lane; q < cnt; q += 32) {
            int e = off + q;
            if (e < E_MAXSZ) {
                int j = s_rowj[local][q];
                out[OFF_EDGES + 2 * (size_t)e + 0] = ti;
                out[OFF_EDGES + 2 * (size_t)e + 1] = g_track[j];
                int tdI = g_trkInt[j];
                int so = atomicAdd(&g_outCnt[tsI], 1);
                if (so < LIST_CAP) g_outList[tsI][so] = e;
                int si = atomicAdd(&g_inCnt[tdI], 1);
                if (si < LIST_CAP) g_inList[tdI][si] = e;
            }
        }
    }

    // slot bookkeeping: y, mask, fill (nonzero fill_value=0 -> track[0])
    if (tid < ROWS_PER_BLK) {
        int s = bid * ROWS_PER_BLK + tid;
        out[OFF_Y + (size_t)s] = 0.0f;
        out[OFF_MASK + (size_t)s] = (s < count) ? 1.0f : 0.0f;
        if (s >= count) {
            float t0 = g_track[0];
            out[OFF_EDGES + 2 * (size_t)s + 0] = t0;
            out[OFF_EDGES + 2 * (size_t)s + 1] = t0;
        }
    }
}

// ---------------------------------------------------------------------------
// K2: scatter the ones into the (already zeroed) Ri/Ro rows.
// grid = 64, block = 256: thread p handles matrix-row pair p of 16384.
// Also resets g_stcnt + barrier counters for the next replay (all readers of
// those live in k_mega, which completed before this launch).
// ---------------------------------------------------------------------------
__global__ void __launch_bounds__(256) k_scatter(float* __restrict__ out) {
    int p = blockIdx.x * 256 + threadIdx.x;

    if (blockIdx.x == 0) {
        if (threadIdx.x < 32) g_stcnt[threadIdx.x] = 0;
        if (threadIdx.x == 32) g_barA = 0;
        if (threadIdx.x == 33) g_barB = 0;
    }
    if (p >= 2 * N_HITS) return;

    int mat = p >> 13;                // 0 = Ri, 1 = Ro
    int row = p & (N_HITS - 1);
    size_t base = (mat == 0 ? OFF_RI : OFF_RO) + (size_t)row * E_MAXSZ;

    int t = g_trkInt[row];
    int c;
    const int* lst;
    if (mat == 0) { c = g_inCnt[t];  lst = g_inList[t];  }
    else          { c = g_outCnt[t]; lst = g_outList[t]; }
    if (c > LIST_CAP) c = LIST_CAP;
    for (int m = 0; m < c; m++)
        out[base + (size_t)lst[m]] = 1.0f;
}

// ---------------------------------------------------------------------------
extern "C" void kernel_launch(void* const* d_in, const int* in_sizes, int n_in,
                              void* d_out, int out_size) {
    const float* ed = (const float*)d_in[0];
    float* out = (float*)d_out;

    k_mega   <<<NBLK + 2 * N_HITS, 256>>>(ed, out);
    k_scatter<<<64, 256>>>(out);
}

// round 9
// speedup vs baseline: 1.1886x; 1.0027x over previous
#include <cuda_runtime.h>
#include <stdint.h>

#define N_HITS  8192
#define E_MAXSZ 8192
#define ROW_CAP 64
#define LIST_CAP 64
#define NBLK 512
#define ROWS_PER_BLK 16     // 512 * 16 = 8192

// Output layout (float32 elements), tuple flattened in order:
// X (8192x3), Ri (8192x8192), Ro (8192x8192), y (8192), edges (8192x2), edge_mask (8192)
#define OFF_X     ((size_t)0)
#define OFF_RI    ((size_t)24576)
#define OFF_RO    (OFF_RI + (size_t)N_HITS * (size_t)E_MAXSZ)
#define OFF_Y     (OFF_RO + (size_t)N_HITS * (size_t)E_MAXSZ)
#define OFF_EDGES (OFF_Y + (size_t)E_MAXSZ)
#define OFF_MASK  (OFF_EDGES + (size_t)2 * E_MAXSZ)

// ---- scratch (device globals; zero-initialized at module load) ----
__device__ float  g_phin[N_HITS];
__device__ float  g_zn[N_HITS];
__device__ float  g_track[N_HITS];
__device__ int    g_trkInt[N_HITS];
__device__ float  g_ev[N_HITS];
__device__ int    g_st[N_HITS];

__device__ int    g_stcnt[32];              // reset in k_scatter (after last reader)
__device__ float4 g_stdata[32][N_HITS];     // {phin, zn, idx_bits, ev}

__device__ int    g_blockSum[NBLK];

// per-track edge lists (counters reset in pipeline phase 0 each run)
__device__ int    g_inCnt[1024];            // edges e with track[dst[e]] == t  -> Ri rows
__device__ int    g_outCnt[1024];           // edges e with track[src[e]] == t  -> Ro rows
__device__ int    g_inList[1024][LIST_CAP];
__device__ int    g_outList[1024][LIST_CAP];

// spin-barrier counters (reset in k_scatter for the next replay)
__device__ int    g_barA;
__device__ int    g_barB;

// ---------------------------------------------------------------------------
// grid-wide barrier for exactly NBLK co-resident pipeline blocks.
// Zero-role blocks never touch it (they retire), so it cannot deadlock as
// long as the NBLK lowest bids are wave-1 resident (guaranteed by
// __launch_bounds__(256,4): 4 * 148 = 592 slots >= NBLK, in-order dispatch).
// ---------------------------------------------------------------------------
__device__ __forceinline__ void grid_bar(int* ctr) {
    __syncthreads();
    if (threadIdx.x == 0) {
        __threadfence();                       // release: publish prior writes
        atomicAdd(ctr, 1);
        while (*(volatile int*)ctr < NBLK) { __nanosleep(64); }
        __threadfence();                       // acquire
    }
    __syncthreads();
}

// ---------------------------------------------------------------------------
// K1: mega kernel.
//   bids [0, NBLK)            : fused pipeline (prep -> pairs -> scan+emit)
//   bids [NBLK, NBLK+16384)   : zero one Ri/Ro row and retire (no dependence
//                               on the pipeline; overlaps it for free)
// ---------------------------------------------------------------------------
__global__ void __launch_bounds__(256, 4) k_mega(const float* __restrict__ ed,
                                                 float* __restrict__ out) {
    __shared__ int s_rowj[ROWS_PER_BLK][ROW_CAP];   // 4 KB
    __shared__ int s_rowcnt[ROWS_PER_BLK];
    __shared__ int s_bs[NBLK];                      // 2 KB
    __shared__ int s_pfx[256];                      // 1 KB
    __shared__ int s_wt[8];
    __shared__ int s_count;

    int tid  = threadIdx.x;
    int bid  = blockIdx.x;

    // ===== zero role: bulk-zero one 8192-float row, then retire =====
    if (bid >= NBLK) {
        int row = bid - NBLK;
        size_t base = (row < N_HITS)
            ? OFF_RI + (size_t)row * E_MAXSZ
            : OFF_RO + (size_t)(row - N_HITS) * E_MAXSZ;
        float4* p = (float4*)(out + base);
        const float4 z4 = make_float4(0.f, 0.f, 0.f, 0.f);
        #pragma unroll
        for (int k = 0; k < 8; k++)
            p[k * 256 + tid] = z4;
        return;
    }

    int lane = tid & 31;
    int wid  = tid >> 5;

    // ===== Phase 0: prep (this block's 16 hits) + counter reset =====
    if (tid < ROWS_PER_BLK) {
        int i = bid * ROWS_PER_BLK + tid;

        float ev  = ed[6 * i + 0];
        float x   = ed[6 * i + 1];
        float y   = ed[6 * i + 2];
        float z   = ed[6 * i + 3];
        float stf = ed[6 * i + 4];
        float trk = ed[6 * i + 5];

        // IEEE-exact f32 path (no fma contraction, rn division/sqrt)
        float xx = __fmul_rn(x, x);
        float yy = __fmul_rn(y, y);
        float r  = __fsqrt_rn(__fadd_rn(xx, yy));
        float phi = atan2f(x, y);

        float rn   = __fadd_rn(__fdiv_rn(__fmul_rn(2.0f, __fadd_rn(r,  -269.0f)),  312.0f), -1.0f);
        float phin = __fadd_rn(__fdiv_rn(__fmul_rn(2.0f, __fadd_rn(phi,  3.15f)),    6.3f), -1.0f);
        float zn   = __fadd_rn(__fdiv_rn(__fmul_rn(2.0f, __fadd_rn(z,  2386.0f)),  4772.0f), -1.0f);

        out[OFF_X + 3 * (size_t)i + 0] = rn;
        out[OFF_X + 3 * (size_t)i + 1] = phin;
        out[OFF_X + 3 * (size_t)i + 2] = zn;

        g_phin[i]   = phin;
        g_zn[i]     = zn;
        g_track[i]  = trk;
        g_trkInt[i] = (int)trk;
        g_ev[i]     = ev;
        int st      = (int)stf;
        g_st[i]     = st;

        if (st >= 0 && st < 32) {
            int slot = atomicAdd(&g_stcnt[st], 1);
            float4 d;
            d.x = phin; d.y = zn; d.z = __int_as_float(i); d.w = ev;
            g_stdata[st][slot] = d;
        }
    }
    if (tid < 2) { g_inCnt[bid * 2 + tid] = 0; g_outCnt[bid * 2 + tid] = 0; }

    grid_bar(&g_barA);

    // ===== Phase 1: pairs — warp w handles local rows w and w+8 =====
    #pragma unroll
    for (int half = 0; half < 2; half++) {
        int local = wid + half * 8;
        int row   = bid * ROWS_PER_BLK + local;

        int myMatch[16];
        int mycnt = 0;

        int s2 = g_st[row] + 1;
        if (s2 >= 0 && s2 < 32) {
            int n2 = g_stcnt[s2];
            float pi  = g_phin[row];
            float zi  = g_zn[row];
            float evi = g_ev[row];
            for (int k = lane; k < n2; k += 32) {
                float4 c = g_stdata[s2][k];
                float dphi = c.x - pi;
                float dz   = c.y - zi;
                bool ok = (c.w == evi) &
                          (dphi > -0.04f) & (dphi < 0.04f) &
                          (dz   > -0.03f) & (dz   < 0.03f);
                if (ok && mycnt < 16) myMatch[mycnt++] = __float_as_int(c.z);
            }
        }

        // warp exclusive scan of per-lane counts
        int off = mycnt;
        #pragma unroll
        for (int d = 1; d < 32; d <<= 1) {
            int v = __shfl_up_sync(0xFFFFFFFFu, off, d);
            if (lane >= d) off += v;
        }
        int total = __shfl_sync(0xFFFFFFFFu, off, 31);
        int excl  = off - mycnt;
        for (int m = 0; m < mycnt; m++) {
            int e = excl + m;
            if (e < ROW_CAP) s_rowj[local][e] = myMatch[m];
        }
        __syncwarp();

        if (lane == 0) {
            int cnt = total < ROW_CAP ? total : ROW_CAP;
            // insertion sort ascending by j (bucket order nondeterministic;
            // restores exact row-major nonzero order)
            for (int a = 1; a < cnt; a++) {
                int v = s_rowj[local][a];
                int b = a - 1;
                while (b >= 0 && s_rowj[local][b] > v) { s_rowj[local][b + 1] = s_rowj[local][b]; b--; }
                s_rowj[local][b + 1] = v;
            }
            s_rowcnt[local] = cnt;
        }
        __syncwarp();
    }

    __syncthreads();
    if (tid == 0) {
        int sum = 0;
        #pragma unroll
        for (int m = 0; m < ROWS_PER_BLK; m++) sum += s_rowcnt[m];
        g_blockSum[bid] = sum;
    }

    grid_bar(&g_barB);

    // ===== Phase 2: decoupled scan of block sums, then emit =====
    s_bs[tid]       = g_blockSum[tid];
    s_bs[tid + 256] = g_blockSum[tid + 256];
    __syncthreads();

    int pairSum = s_bs[2 * tid] + s_bs[2 * tid + 1];
    int inc = pairSum;
    #pragma unroll
    for (int d = 1; d < 32; d <<= 1) {
        int v = __shfl_up_sync(0xFFFFFFFFu, inc, d);
        if (lane >= d) inc += v;
    }
    if (lane == 31) s_wt[wid] = inc;
    __syncthreads();
    if (wid == 0 && lane < 8) {
        int w = s_wt[lane];
        int wi = w;
        #pragma unroll
        for (int d = 1; d < 8; d <<= 1) {
            int v = __shfl_up_sync(0xFFu, wi, d);
            if (lane >= d) wi += v;
        }
        s_wt[lane] = wi - w;      // exclusive warp offsets
        if (lane == 7) s_count = wi;
    }
    __syncthreads();
    int pairExcl = inc - pairSum + s_wt[wid];
    s_pfx[tid] = pairExcl;
    __syncthreads();

    int count   = s_count;
    int blkBase = s_pfx[bid >> 1] + ((bid & 1) ? s_bs[bid - 1] : 0);

    // emit: warp w handles local rows w and w+8
    #pragma unroll
    for (int half = 0; half < 2; half++) {
        int local = wid + half * 8;
        int row   = bid * ROWS_PER_BLK + local;
        int cnt   = s_rowcnt[local];

        int off = blkBase;
        for (int m = 0; m < local; m++) off += s_rowcnt[m];

        float ti = g_track[row];
        int  tsI = g_trkInt[row];

        for (int q = lane; q < cnt; q += 32) {
            int e = off + q;
            if (e < E_MAXSZ) {
                int j = s_rowj[local][q];
                out[OFF_EDGES + 2 * (size_t)e + 0] = ti;
                out[OFF_EDGES + 2 * (size_t)e + 1] = g_track[j];
                int tdI = g_trkInt[j];
                int so = atomicAdd(&g_outCnt[tsI], 1);
                if (so < LIST_CAP) g_outList[tsI][so] = e;
                int si = atomicAdd(&g_inCnt[tdI], 1);
                if (si < LIST_CAP) g_inList[tdI][si] = e;
            }
        }
    }

    // slot bookkeeping: y, mask, fill (nonzero fill_value=0 -> track[0])
    if (tid < ROWS_PER_BLK) {
        int s = bid * ROWS_PER_BLK + tid;
        out[OFF_Y + (size_t)s] = 0.0f;
        out[OFF_MASK + (size_t)s] = (s < count) ? 1.0f : 0.0f;
        if (s >= count) {
            float t0 = g_track[0];
            out[OFF_EDGES + 2 * (size_t)s + 0] = t0;
            out[OFF_EDGES + 2 * (size_t)s + 1] = t0;
        }
    }
}

// ---------------------------------------------------------------------------
// K2: scatter the ones into the (already zeroed) Ri/Ro rows.
// One WARP per (matrix,row) pair: 16384 warps = 2048 blocks x 8 warps.
// Lanes stride the per-track edge list -> all stores issue in parallel.
// Also resets g_stcnt + barrier counters for the next replay (all readers of
// those live in k_mega, which completed before this launch).
// ---------------------------------------------------------------------------
__global__ void __launch_bounds__(256) k_scatter(float* __restrict__ out) {
    int gwarp = (blockIdx.x * 256 + threadIdx.x) >> 5;   // 0 .. 16383
    int lane  = threadIdx.x & 31;

    if (blockIdx.x == 0) {
        if (threadIdx.x < 32) g_stcnt[threadIdx.x] = 0;
        if (threadIdx.x == 32) g_barA = 0;
        if (threadIdx.x == 33) g_barB = 0;
    }

    int mat = gwarp >> 13;                // 0 = Ri, 1 = Ro
    int row = gwarp & (N_HITS - 1);
    size_t base = (mat == 0 ? OFF_RI : OFF_RO) + (size_t)row * E_MAXSZ;

    int t = g_trkInt[row];
    int c;
    const int* lst;
    if (mat == 0) { c = g_inCnt[t];  lst = g_inList[t];  }
    else          { c = g_outCnt[t]; lst = g_outList[t]; }
    if (c > LIST_CAP) c = LIST_CAP;
    for (int m = lane; m < c; m += 32)
        out[base + (size_t)lst[m]] = 1.0f;
}

// ---------------------------------------------------------------------------
extern "C" void kernel_launch(void* const* d_in, const int* in_sizes, int n_in,
                              void* d_out, int out_size) {
    const float* ed = (const float*)d_in[0];
    float* out = (float*)d_out;

    k_mega   <<<NBLK + 2 * N_HITS, 256>>>(ed, out);
    k_scatter<<<2048, 256>>>(out);
}